// round 1
// baseline (speedup 1.0000x reference)
#include <cuda_runtime.h>
#include <cstdint>

// Problem constants (fixed by the reference)
#define M_ROWS 16384
#define IN_F   2048
#define OUT_F  2048

// Scratch: indices of negative-weight entries per output row, plus counts.
// Exact identity used:
//   out[m,n] = rowsum(x[m]) - 2 * sum_{k: w[n,k] < 0} x[m,k]
// which holds for any x and any w, since b_weight = sign(sign(w)+0.5) is -1
// exactly when w < 0 and +1 otherwise (including w == 0).
__device__ unsigned short g_neg_idx[(size_t)OUT_F * IN_F];  // 8 MB
__device__ int            g_neg_cnt[OUT_F];

// ---------------------------------------------------------------------------
// Kernel 1: scan weight rows, collect negative-entry indices.
// One block per output feature n. Rewrites counts every launch (graph-replay
// safe, no persistent state assumptions).
// ---------------------------------------------------------------------------
__global__ void __launch_bounds__(256) scan_weight_kernel(
    const float* __restrict__ w)
{
    const int n = blockIdx.x;
    __shared__ int s_cnt;
    if (threadIdx.x == 0) s_cnt = 0;
    __syncthreads();

    const float* wr = w + (size_t)n * IN_F;
    unsigned short* idx = g_neg_idx + (size_t)n * IN_F;

    // Vectorized scan: 2048 floats / 256 threads = 8 per thread (2x float4)
    const float4* wr4 = reinterpret_cast<const float4*>(wr);
    #pragma unroll
    for (int g = 0; g < 2; g++) {
        int i4 = threadIdx.x + g * 256;
        float4 v = wr4[i4];
        int kbase = i4 * 4;
        if (v.x < 0.0f) { int p = atomicAdd(&s_cnt, 1); idx[p] = (unsigned short)(kbase + 0); }
        if (v.y < 0.0f) { int p = atomicAdd(&s_cnt, 1); idx[p] = (unsigned short)(kbase + 1); }
        if (v.z < 0.0f) { int p = atomicAdd(&s_cnt, 1); idx[p] = (unsigned short)(kbase + 2); }
        if (v.w < 0.0f) { int p = atomicAdd(&s_cnt, 1); idx[p] = (unsigned short)(kbase + 3); }
    }
    __syncthreads();
    if (threadIdx.x == 0) g_neg_cnt[n] = s_cnt;
}

// ---------------------------------------------------------------------------
// Kernel 2: per x-row: stage row in smem, compute rowsum, emit OUT_F outputs
// with the negative-set correction. One block per m. Pure HBM streaming when
// the negative sets are empty.
// ---------------------------------------------------------------------------
__global__ void __launch_bounds__(256) bnn_out_kernel(
    const float* __restrict__ x,
    float*       __restrict__ out)
{
    const int m = blockIdx.x;
    __shared__ float sx[IN_F];
    __shared__ float warp_sums[8];
    __shared__ float s_total;

    const float4* xr4 = reinterpret_cast<const float4*>(x + (size_t)m * IN_F);
    float4 a = xr4[threadIdx.x];
    float4 b = xr4[threadIdx.x + 256];
    reinterpret_cast<float4*>(sx)[threadIdx.x]       = a;
    reinterpret_cast<float4*>(sx)[threadIdx.x + 256] = b;

    float s = ((a.x + a.y) + (a.z + a.w)) + ((b.x + b.y) + (b.z + b.w));
    #pragma unroll
    for (int o = 16; o > 0; o >>= 1)
        s += __shfl_xor_sync(0xffffffffu, s, o);
    if ((threadIdx.x & 31) == 0) warp_sums[threadIdx.x >> 5] = s;
    __syncthreads();
    if (threadIdx.x == 0) {
        float t = 0.0f;
        #pragma unroll
        for (int i = 0; i < 8; i++) t += warp_sums[i];
        s_total = t;
    }
    __syncthreads();

    const float S = s_total;
    float* orow = out + (size_t)m * OUT_F;

    // 2048 outputs / 256 threads = 8 per thread (2x float4 stores)
    #pragma unroll
    for (int g = 0; g < 2; g++) {
        const int n0 = g * 1024 + threadIdx.x * 4;
        const int4 c4 = reinterpret_cast<const int4*>(g_neg_cnt)[n0 >> 2];
        float4 v;
        {
            float c = 0.0f;
            const unsigned short* id = g_neg_idx + (size_t)(n0 + 0) * IN_F;
            for (int j = 0; j < c4.x; j++) c += sx[id[j]];
            v.x = S - 2.0f * c;
        }
        {
            float c = 0.0f;
            const unsigned short* id = g_neg_idx + (size_t)(n0 + 1) * IN_F;
            for (int j = 0; j < c4.y; j++) c += sx[id[j]];
            v.y = S - 2.0f * c;
        }
        {
            float c = 0.0f;
            const unsigned short* id = g_neg_idx + (size_t)(n0 + 2) * IN_F;
            for (int j = 0; j < c4.z; j++) c += sx[id[j]];
            v.z = S - 2.0f * c;
        }
        {
            float c = 0.0f;
            const unsigned short* id = g_neg_idx + (size_t)(n0 + 3) * IN_F;
            for (int j = 0; j < c4.w; j++) c += sx[id[j]];
            v.w = S - 2.0f * c;
        }
        reinterpret_cast<float4*>(orow)[n0 >> 2] = v;
    }
}

// ---------------------------------------------------------------------------
// kernel_launch: inputs per metadata order: d_in[0] = x [M, IN_F] fp32,
// d_in[1] = weight [OUT_F, IN_F] fp32. d_out = [M, OUT_F] fp32.
// ---------------------------------------------------------------------------
extern "C" void kernel_launch(void* const* d_in, const int* in_sizes, int n_in,
                              void* d_out, int out_size)
{
    const float* x = (const float*)d_in[0];
    const float* w = (const float*)d_in[1];
    float* out = (float*)d_out;

    scan_weight_kernel<<<OUT_F, 256>>>(w);
    bnn_out_kernel<<<M_ROWS, 256>>>(x, out);
}